// round 9
// baseline (speedup 1.0000x reference)
#include <cuda_runtime.h>

// SpringMass: B=4096 independent 2-state linear ODEs, T=4096 RK4 steps each.
// Affine scan over time (pass1 compose / pass2 block scan / pass3 replay),
// two 2048-step halves with carried (v,x) state.
//
// R9 change: occupancy push. regs 48 capped residency at 10 CTAs/SM
// (occ 56%, issue 66%, nothing saturated => warp-supply bound). Force
// launch_bounds(128,12) -> regs<=42 -> 12 CTAs = 48 warps/SM. Scan live
// ranges reordered (exclusive shfl hoisted before the wsum prefix loop)
// to help ptxas reach 42 without spilling.

#define T_LEN  4096
#define NTHR   128
#define HALF   (T_LEN / 2)        // 2048 steps per phase
#define F4C    8                  // input float4 per chunk per half
#define O4C    4                  // output float4 per chunk per half

namespace sm_consts {
constexpr double Cd = 0.1, dd = 0.01;
// A = alpha(k)*I + beta(k)*B, B=[[-C,-k],[1,0]] (deg-4 Taylor of exp(dt B))
constexpr double AL1d = -dd*dd/2.0 + Cd*dd*dd*dd/6.0 - Cd*Cd*dd*dd*dd*dd/24.0;
constexpr double AL2d = dd*dd*dd*dd/24.0;
constexpr double BE0d = dd - Cd*dd*dd/2.0 + Cd*Cd*dd*dd*dd/6.0 - Cd*Cd*Cd*dd*dd*dd*dd/24.0;
constexpr double BE1d = -dd*dd*dd/6.0 + Cd*dd*dd*dd*dd/12.0;
// forcing: g = c0*e1 + c1*B*e1, B*e1 = (-C,1)
constexpr double C00 = dd;
constexpr double C01 = dd*(-dd*dd/6.0 + dd*dd*dd*Cd/24.0);
constexpr double C10 = dd*(dd/2.0 - dd*dd*Cd/6.0 + dd*dd*dd*Cd*Cd/24.0);
constexpr double C11 = dd*(-dd*dd*dd/24.0);

constexpr float AL1 = (float)AL1d;
constexpr float AL2 = (float)AL2d;
constexpr float BE0 = (float)BE0d;
constexpr float BE1 = (float)BE1d;
constexpr float KG10 = (float)(C00 - Cd*C10);   // g1 = KG10 + KG11*k
constexpr float KG11 = (float)(C01 - Cd*C11);
constexpr float KG20 = (float)C10;              // g2 = KG20 + KG21*k
constexpr float KG21 = (float)C11;
constexpr float CF   = 0.1f;
}  // namespace sm_consts

struct Aff { float a11, a12, a21, a22, b1, b2; };

__device__ __forceinline__ Aff compose(const Aff& n, const Aff& o) {
    Aff r;
    r.a11 = fmaf(n.a11, o.a11, n.a12 * o.a21);
    r.a12 = fmaf(n.a11, o.a12, n.a12 * o.a22);
    r.a21 = fmaf(n.a21, o.a11, n.a22 * o.a21);
    r.a22 = fmaf(n.a21, o.a12, n.a22 * o.a22);
    r.b1  = fmaf(n.a11, o.b1, fmaf(n.a12, o.b2, n.b1));
    r.b2  = fmaf(n.a21, o.b1, fmaf(n.a22, o.b2, n.b2));
    return r;
}

__device__ __forceinline__ Aff step_map(float k, float F) {
    using namespace sm_consts;
    Aff s;
    float al = fmaf(fmaf(AL2, k, AL1), k, 1.0f);
    float be = fmaf(BE1, k, BE0);
    s.a11 = fmaf(-CF, be, al);
    s.a12 = -k * be;
    s.a21 = be;
    s.a22 = al;
    s.b1 = F * fmaf(KG11, k, KG10);
    s.b2 = F * fmaf(KG21, k, KG20);
    return s;
}

// advance state, return xddot for this step (computed from NEW state)
__device__ __forceinline__ float step_state(float k, float F, float& v, float& x) {
    using namespace sm_consts;
    float al = fmaf(fmaf(AL2, k, AL1), k, 1.0f);
    float be = fmaf(BE1, k, BE0);
    float A11 = fmaf(-CF, be, al);
    float A12 = -k * be;
    float g1  = fmaf(KG11, k, KG10);
    float g2  = fmaf(KG21, k, KG20);
    float vn = fmaf(A11, v, fmaf(A12, x, F * g1));
    float xn = fmaf(be,  v, fmaf(al,  x, F * g2));
    v = vn; x = xn;
    return fmaf(-k, xn, fmaf(-CF, vn, F));
}

__device__ __forceinline__ Aff shfl_up_aff(const Aff& m, int off) {
    Aff r;
    r.a11 = __shfl_up_sync(0xffffffffu, m.a11, off);
    r.a12 = __shfl_up_sync(0xffffffffu, m.a12, off);
    r.a21 = __shfl_up_sync(0xffffffffu, m.a21, off);
    r.a22 = __shfl_up_sync(0xffffffffu, m.a22, off);
    r.b1  = __shfl_up_sync(0xffffffffu, m.b1,  off);
    r.b2  = __shfl_up_sync(0xffffffffu, m.b2,  off);
    return r;
}

// smem slot for (chunk c, float4 offset o): XOR swizzle keeps per-chunk
// strided reads conflict-free per 8-lane LDS.128 phase.
__device__ __forceinline__ int slot(int c, int o) {
    return c * F4C + (o ^ (c & 7));
}

__global__ void __launch_bounds__(NTHR, 12)
spring_scan_kernel(const float* __restrict__ in,
                   const float* __restrict__ vinit,
                   const float* __restrict__ xinit,
                   float* __restrict__ out) {
    __shared__ float4 buf[NTHR * F4C];     // 16 KB half-row tile
    __shared__ Aff wsum[NTHR / 32];

    const int b = blockIdx.x;
    const int l = threadIdx.x;
    const int lane = l & 31;
    const int w = l >> 5;

    const float4* gin  = reinterpret_cast<const float4*>(in + (long)b * T_LEN * 2);
    float4*       gout = reinterpret_cast<float4*>(out + (long)b * T_LEN);

    float vh = vinit[b], xh = xinit[b];    // state entering current half

#pragma unroll 1
    for (int half = 0; half < 2; half++) {
        const float4* gin_h  = gin  + half * (HALF / 2);   // 1024 float4 per half
        float4*       gout_h = gout + half * (HALF / 4);   // 512 float4 per half

        // ---- Stage: coalesced global -> swizzled smem ----
#pragma unroll
        for (int r = 0; r < F4C; r++) {
            int idx = r * NTHR + l;
            buf[slot(idx >> 3, idx & 7)] = gin_h[idx];
        }
        __syncthreads();

        // ---- Pass 1: compose this thread's 16-step chunk map ----
        Aff M = {1.f, 0.f, 0.f, 1.f, 0.f, 0.f};
#pragma unroll 4
        for (int o = 0; o < F4C; o++) {
            float4 d = buf[slot(l, o)];
            M = compose(step_map(d.x, d.y), M);
            M = compose(step_map(d.z, d.w), M);
        }

        // ---- Pass 2: block-wide scan ----
#pragma unroll
        for (int off = 1; off < 32; off <<= 1) {
            Aff o = shfl_up_aff(M, off);
            if (lane >= off) M = compose(M, o);
        }

        // exclusive in-warp value first (shortens M's live range)
        Aff eo = shfl_up_aff(M, 1);
        Aff excl;
        if (lane == 0) { excl.a11 = 1.f; excl.a12 = 0.f; excl.a21 = 0.f;
                         excl.a22 = 1.f; excl.b1 = 0.f;  excl.b2 = 0.f; }
        else           { excl = eo; }

        if (lane == 31) wsum[w] = M;
        __syncthreads();

        // prefix over preceding warps + total half map (for the carry)
        Aff pre    = {1.f, 0.f, 0.f, 1.f, 0.f, 0.f};
        Aff preAll = {1.f, 0.f, 0.f, 1.f, 0.f, 0.f};
#pragma unroll
        for (int j = 0; j < NTHR / 32; j++) {
            if (j == w) pre = preAll;
            preAll = compose(wsum[j], preAll);
        }

        Aff tot = compose(excl, pre);      // exclusive prefix within half

        // state entering this thread's chunk
        float v = fmaf(tot.a11, vh, fmaf(tot.a12, xh, tot.b1));
        float x = fmaf(tot.a21, vh, fmaf(tot.a22, xh, tot.b2));

        // carry: state entering the next half
        float vh2 = fmaf(preAll.a11, vh, fmaf(preAll.a12, xh, preAll.b1));
        float xh2 = fmaf(preAll.a21, vh, fmaf(preAll.a22, xh, preAll.b2));
        vh = vh2; xh = xh2;

        // ---- Pass 3: replay chunk, write xddot in place ----
        // Output float4 j consumes input float4s 2j,2j+1; overwrites slot j
        // (j <= 2j: already consumed). Chunks are thread-private, no hazard.
#pragma unroll 2
        for (int j = 0; j < O4C; j++) {
            float4 d0 = buf[slot(l, 2 * j)];
            float4 d1 = buf[slot(l, 2 * j + 1)];
            float4 o4;
            o4.x = step_state(d0.x, d0.y, v, x);
            o4.y = step_state(d0.z, d0.w, v, x);
            o4.z = step_state(d1.x, d1.y, v, x);
            o4.w = step_state(d1.z, d1.w, v, x);
            buf[slot(l, j)] = o4;
        }
        __syncthreads();

        // ---- Drain: swizzled smem -> coalesced global store ----
#pragma unroll
        for (int r = 0; r < O4C; r++) {
            int idx = r * NTHR + l;
            gout_h[idx] = buf[slot(idx >> 2, idx & 3)];
        }
        if (half == 0) __syncthreads();    // buf + wsum reuse in next half
    }
}

extern "C" void kernel_launch(void* const* d_in, const int* in_sizes, int n_in,
                              void* d_out, int out_size) {
    const float* in = (const float*)d_in[0];       // (B, T, 2) float32
    const float* vi = (const float*)d_in[1];       // (B, 1)
    const float* xi = (const float*)d_in[2];       // (B, 1)
    float* out = (float*)d_out;                    // (B, T, 1) float32
    const int B = in_sizes[1];                     // 4096
    spring_scan_kernel<<<B, NTHR>>>(in, vi, xi, out);
}